// round 6
// baseline (speedup 1.0000x reference)
#include <cuda_runtime.h>
#include <math.h>

#define NB   16
#define CINC 256
#define DIMC 32
#define HH   128
#define WW   128
#define PIX  (HH*WW)          // 16384
#define NA   192
#define NR   192
#define APIX (NA*NR)          // 36864
#define BN_EPS 1e-5f
#define RUNCAP 132

typedef unsigned long long ull;

__device__ __forceinline__ void fma2(ull& d, ull a, ull b) {
    asm("fma.rn.f32x2 %0, %1, %2, %0;" : "+l"(d) : "l"(a), "l"(b));
}
__device__ __forceinline__ ull pack2(float x) {
    ull r; asm("mov.b64 %0, {%1, %1};" : "=l"(r) : "f"(x)); return r;
}
__device__ __forceinline__ void unpack2(ull v, float& lo, float& hi) {
    asm("mov.b64 {%0, %1}, %2;" : "=f"(lo), "=f"(hi) : "l"(v));
}

// ---------------- device scratch ----------------
__device__ unsigned int  g_runs[(size_t)NA * HH * RUNCAP];      // [a][line][slot] = t | r<<8
__device__ int           g_nrun[NA * HH];
__device__ float         g_h1[(size_t)NB * PIX * DIMC];         // [n][p][c]
__device__ float         g_pref[(size_t)NB * HH * 129 * DIMC];  // [n][y][x+1][c]
__device__ float         g_prefy[(size_t)NB * HH * 129 * DIMC]; // [n][x][y+1][c]
__device__ float         g_acc[(size_t)NB * DIMC * NA * NR];    // [n][c][a][r]
__device__ float         g_h2[(size_t)NB * DIMC * NA * NR];
__device__ float         g_part1[512  * DIMC * 2];
__device__ float         g_part2[2304 * DIMC * 2];
__device__ float         g_part3[2304 * DIMC * 2];
__device__ float         g_scale2[DIMC], g_shift2[DIMC];
__device__ float         g_scale3[DIMC], g_shift3[DIMC];

// ---------------- run-list builder, dual-axis --------------------------------
// x-mode (48<=a<144): runs along x at fixed y=line. Else runs along y at x=line.
__global__ void k_runs() {
    __shared__ int sr[128];
    __shared__ int swcnt[4];
    __shared__ int swoff[4];
    int a = blockIdx.x, line = blockIdx.y;
    int t = threadIdx.x;
    double irho = 182.0 / 191.0;
    double th = (double)a * (3.141592653589793 / 192.0);
    double tc = cos(th) / irho;
    double ts = sin(th) / irho;
    bool xmode = (a >= 48 && a < 144);
    int xc = xmode ? t : line;
    int yc = xmode ? line : t;
    // identical op order to numpy: mul, mul, add in double; rint = half-even
    double v = __dadd_rn(__dmul_rn((double)(xc - 64), tc),
                         __dmul_rn((double)(yc - 64), ts));
    int r = (int)rint(v) + 96;
    r = min(max(r, 0), 191);
    sr[t] = r;
    __syncthreads();
    int f = (t == 0) || (r != sr[t - 1]);
    unsigned bal = __ballot_sync(0xffffffffu, f);
    int w = t >> 5, lane = t & 31;
    int pre = __popc(bal & ((1u << lane) - 1u));
    if (lane == 31) swcnt[w] = __popc(bal);
    __syncthreads();
    if (t == 0) {
        int o = 0;
        for (int i = 0; i < 4; i++) { swoff[i] = o; o += swcnt[i]; }
        g_nrun[a * HH + line] = o;
        g_runs[((size_t)a * HH + line) * RUNCAP + o] = 128u;   // sentinel
    }
    __syncthreads();
    if (f) g_runs[((size_t)a * HH + line) * RUNCAP + swoff[w] + pre] =
               (unsigned)t | ((unsigned)r << 8);
}

// ---------------- conv1 (1x1, FFMA2) + BN1 partial stats --------------------
__global__ __launch_bounds__(256) void k_conv1(const float* __restrict__ x,
                                               const float* __restrict__ w1,
                                               const float* __restrict__ b1) {
    __shared__ float sW[CINC * DIMC];
    __shared__ float sX[4][512];
    __shared__ float sS[DIMC], sQ[DIMC];

    int tid = threadIdx.x;
    int n  = blockIdx.x >> 5;
    int p0 = (blockIdx.x & 31) * 512;

    for (int i = tid; i < CINC * DIMC; i += 256) {
        int ci = i >> 5, d = i & 31;
        sW[i] = w1[d * CINC + ci];
    }
    if (tid < DIMC) { sS[tid] = 0.f; sQ[tid] = 0.f; }

    int pl = tid & 63;
    int d0 = (tid >> 6) * 8;

    ull acc2[8][4];
#pragma unroll
    for (int j = 0; j < 8; j++)
#pragma unroll
        for (int k = 0; k < 4; k++) acc2[j][k] = 0ull;

    const float* xb = x + (size_t)n * CINC * PIX + p0;

    for (int cc = 0; cc < CINC; cc += 4) {
        __syncthreads();
        for (int i = tid; i < 4 * 512; i += 256) {
            int cl = i >> 9, pp = i & 511;
            sX[cl][pp] = xb[(size_t)(cc + cl) * PIX + pp];
        }
        __syncthreads();
#pragma unroll
        for (int cl = 0; cl < 4; cl++) {
            float xv[8];
#pragma unroll
            for (int j = 0; j < 8; j++) xv[j] = sX[cl][pl + 64 * j];
            const ull* wp = (const ull*)&sW[(cc + cl) * DIMC + d0];
            ull w0 = wp[0], w1r = wp[1], w2 = wp[2], w3 = wp[3];
#pragma unroll
            for (int j = 0; j < 8; j++) {
                ull xp = pack2(xv[j]);
                fma2(acc2[j][0], xp, w0);
                fma2(acc2[j][1], xp, w1r);
                fma2(acc2[j][2], xp, w2);
                fma2(acc2[j][3], xp, w3);
            }
        }
    }

    float bia[8];
#pragma unroll
    for (int k = 0; k < 8; k++) bia[k] = b1[d0 + k];

    float* hb = g_h1 + ((size_t)n * PIX + p0) * DIMC;
    float sl[8], ql[8];
#pragma unroll
    for (int k = 0; k < 8; k++) { sl[k] = 0.f; ql[k] = 0.f; }

#pragma unroll
    for (int j = 0; j < 8; j++) {
        float vv[8];
#pragma unroll
        for (int k2 = 0; k2 < 4; k2++) {
            float lo, hi;
            unpack2(acc2[j][k2], lo, hi);
            vv[2 * k2]     = lo + bia[2 * k2];
            vv[2 * k2 + 1] = hi + bia[2 * k2 + 1];
        }
#pragma unroll
        for (int k = 0; k < 8; k++) { sl[k] += vv[k]; ql[k] += vv[k] * vv[k]; }
        float* op = hb + (size_t)(pl + 64 * j) * DIMC + d0;
        *(float4*)op       = make_float4(vv[0], vv[1], vv[2], vv[3]);
        *(float4*)(op + 4) = make_float4(vv[4], vv[5], vv[6], vv[7]);
    }
#pragma unroll
    for (int k = 0; k < 8; k++) {
        atomicAdd(&sS[d0 + k], sl[k]);
        atomicAdd(&sQ[d0 + k], ql[k]);
    }
    __syncthreads();
    if (tid < DIMC) {
        g_part1[(blockIdx.x * DIMC + tid) * 2 + 0] = sS[tid];
        g_part1[(blockIdx.x * DIMC + tid) * 2 + 1] = sQ[tid];
    }
}

// ---------------- BN reduce (stages 2,3) -------------------------------------
__global__ void k_red(int which, int nb, float cnt,
                      const float* __restrict__ g, const float* __restrict__ be) {
    const float* part = (which == 2) ? g_part2 : g_part3;
    float* sc = (which == 2) ? g_scale2 : g_scale3;
    float* sh = (which == 2) ? g_shift2 : g_shift3;
    __shared__ float rs[8][32], rq[8][32];
    int ch = threadIdx.x & 31, s = threadIdx.x >> 5;
    float su = 0.f, q = 0.f;
    for (int b = s; b < nb; b += 8) {
        su += part[((size_t)b * DIMC + ch) * 2 + 0];
        q  += part[((size_t)b * DIMC + ch) * 2 + 1];
    }
    rs[s][ch] = su; rq[s][ch] = q;
    __syncthreads();
    if (threadIdx.x < 32) {
        float S = 0.f, Q = 0.f;
        for (int t = 0; t < 8; t++) { S += rs[t][ch]; Q += rq[t][ch]; }
        float m   = S / cnt;
        float var = Q / cnt - m * m;
        float scv = g[ch] * rsqrtf(var + BN_EPS);
        sc[ch] = scv;
        sh[ch] = be[ch] - m * scv;
    }
}

// ---------------- both prefix sums (BN1 reduction fused) --------------------
// blocks 0..255: row prefixes (over x). blocks 256..511: column prefixes (over y).
__global__ __launch_bounds__(256) void k_prefboth(const float* __restrict__ g1,
                                                  const float* __restrict__ be1) {
    __shared__ float rs[8][32], rq[8][32], ssc[32], ssh[32];
    int tid = threadIdx.x;
    int ch = tid & 31, s = tid >> 5;
    {
        float su = 0.f, q = 0.f;
        for (int b = s; b < 512; b += 8) {
            su += g_part1[((size_t)b * DIMC + ch) * 2 + 0];
            q  += g_part1[((size_t)b * DIMC + ch) * 2 + 1];
        }
        rs[s][ch] = su; rq[s][ch] = q;
        __syncthreads();
        if (tid < 32) {
            float S = 0.f, Q = 0.f;
            for (int t = 0; t < 8; t++) { S += rs[t][ch]; Q += rq[t][ch]; }
            float cnt = (float)(NB * PIX);
            float m   = S / cnt;
            float var = Q / cnt - m * m;
            float scv = g1[ch] * rsqrtf(var + BN_EPS);
            ssc[ch] = scv;
            ssh[ch] = be1[ch] - m * scv;
        }
        __syncthreads();
    }
    int w = s, c = ch;
    float sc = ssc[c], sh = ssh[c];
    int bid = blockIdx.x;
    if (bid < 256) {
        int row = bid * 8 + w;                    // n*128 + y
        int n = row >> 7, y = row & 127;
        const float* hb = g_h1 + ((size_t)n * PIX + (size_t)y * WW) * DIMC + c;
        float* pb = g_pref + (size_t)row * 129 * DIMC + c;
        float sum = 0.f;
        pb[0] = 0.f;
#pragma unroll 8
        for (int x = 0; x < 128; x++) {
            float v = fmaxf(fmaf(hb[(size_t)x * DIMC], sc, sh), 0.f);
            sum += v;
            pb[(size_t)(x + 1) * DIMC] = sum;
        }
    } else {
        int idx = (bid - 256) * 8 + w;            // n*128 + x
        int n = idx >> 7, x = idx & 127;
        const float* hb = g_h1 + ((size_t)n * PIX + x) * DIMC + c;
        float* pb = g_prefy + (size_t)idx * 129 * DIMC + c;
        float sum = 0.f;
        pb[0] = 0.f;
#pragma unroll 8
        for (int y = 0; y < 128; y++) {
            float v = fmaxf(fmaf(hb[(size_t)y * WW * DIMC], sc, sh), 0.f);
            sum += v;
            pb[(size_t)(y + 1) * DIMC] = sum;
        }
    }
}

// ---------------- DHT gather: dual-axis runs, 16ch/block, carry chunks -------
// grid (48, 2, NB): 4 angles x channel-half x batch. 512 thr, 4 warps/angle.
__global__ __launch_bounds__(512) void k_dhtg() {
    extern __shared__ float sm[];
    float*    sAcc  = sm;                                    // [4][192][20]
    float4*   sRow  = (float4*)(sm + 4 * 192 * 20);          // [2][520]
    unsigned* sRuns = (unsigned*)(sRow + 2 * 520);           // [2][528]
    int*      sNr   = (int*)(sRuns + 2 * 528);               // [2][4]

    int tid = threadIdx.x;
    int n = blockIdx.z, ch0 = blockIdx.y * 16, a0 = blockIdx.x * 4;
    bool xmode = (a0 >= 48 && a0 < 144);

    for (int i = tid; i < 4 * 192 * 20; i += 512) sAcc[i] = 0.f;

    int w = tid >> 5, lane = tid & 31;
    int ga = w >> 2, ws = w & 3;
    int rsub = lane >> 2, c4 = lane & 3;
    int slot = ws * 8 + rsub;                    // 0..31 per angle

    const float4* prefn = (const float4*)((xmode ? g_pref : g_prefy)
                                          + (size_t)n * HH * 129 * DIMC);
    int cbase = (int)blockIdx.y * 4;             // float4 offset of channel half
    float* accA = sAcc + ga * 192 * 20;

    float4 ra, rc;
    unsigned ru0 = 0, ru1 = 0;
    int rn = 0;
    int aa0 = tid / RUNCAP, kk0 = tid - aa0 * RUNCAP;
    int idx1 = tid + 512;
    int aa1 = idx1 / RUNCAP, kk1 = idx1 - aa1 * RUNCAP;
    int m0 = (tid >> 2) * 8 + cbase + (tid & 3);
    int m1 = 128 * 8 + cbase + tid;              // for tid<4 (entries 512..515)

    {   // prefetch line 0
        ra = prefn[m0];
        if (tid < 4) rc = prefn[m1];
        ru0 = g_runs[((size_t)(a0 + aa0) * HH + 0) * RUNCAP + kk0];
        if (tid < 16) ru1 = g_runs[((size_t)(a0 + aa1) * HH + 0) * RUNCAP + kk1];
        if (tid < 4)  rn  = g_nrun[(a0 + tid) * HH + 0];
    }

    for (int line = 0; line < 128; line++) {
        int bsel = line & 1;
        float4* buf = sRow + bsel * 520;
        unsigned* rbuf = sRuns + bsel * 528;
        buf[tid] = ra;
        if (tid < 4) buf[512 + tid] = rc;
        rbuf[tid] = ru0;
        if (tid < 16) rbuf[512 + tid] = ru1;
        if (tid < 4)  sNr[bsel * 4 + tid] = rn;
        __syncthreads();

        if (line < 127) {
            const float4* src = prefn + (size_t)(line + 1) * (129 * 8);
            ra = src[m0];
            if (tid < 4) rc = src[m1];
            ru0 = g_runs[((size_t)(a0 + aa0) * HH + line + 1) * RUNCAP + kk0];
            if (tid < 16) ru1 = g_runs[((size_t)(a0 + aa1) * HH + line + 1) * RUNCAP + kk1];
            if (tid < 4)  rn  = g_nrun[(a0 + tid) * HH + line + 1];
        }

        int nrun = sNr[bsel * 4 + ga];
        const unsigned* rl = rbuf + ga * RUNCAP;
        int chunk = (nrun + 31) >> 5;
        int lo = slot * chunk;
        int hi = min(lo + chunk, nrun);
        if (lo < nrun) {
            float4 ps = buf[(int)(rl[lo] & 255u) * 4 + c4];
            for (int i = lo; i < hi; i++) {
                unsigned rec = rl[i];
                int r  = (rec >> 8) & 255;
                int xe = (int)(rl[i + 1] & 255u);
                float4 pe = buf[xe * 4 + c4];
                float* ap = accA + r * 20 + c4 * 4;
                float4 av = *(float4*)ap;
                av.x += pe.x - ps.x; av.y += pe.y - ps.y;
                av.z += pe.z - ps.z; av.w += pe.w - ps.w;
                *(float4*)ap = av;
                ps = pe;
            }
        }
    }
    __syncthreads();

    for (int e = tid; e < 4 * 16 * NR; e += 512) {
        int r = e % NR;
        int t2 = e / NR;            // 0..63
        int c = t2 & 15, ga2 = t2 >> 4;
        g_acc[(((size_t)n * DIMC + ch0 + c) * NA + (a0 + ga2)) * NR + r] =
            sAcc[(ga2 * 192 + r) * 20 + c];
    }
}

// ---------------- 3x3 conv (FFMA2) — R3 proven version ----------------------
template <int MODE>
__global__ __launch_bounds__(256) void k_conv3x3(const float* __restrict__ w,
                                                 const float* __restrict__ b,
                                                 float* __restrict__ out_ext) {
    extern __shared__ float sm[];
    float* sIn = sm;                 // 32*18*18
    float* sW  = sm + 32 * 324;      // 32*9*32
    __shared__ float sS[DIMC], sQ[DIMC];

    int tid = threadIdx.x;
    if (tid < DIMC) { sS[tid] = 0.f; sQ[tid] = 0.f; }

    int n   = blockIdx.z;
    int ty0 = blockIdx.y * 16, tx0 = blockIdx.x * 16;

    for (int i = tid; i < 32 * 9 * 32; i += 256) {
        int d = i & 31; int t = (i >> 5) % 9; int cc = i / 288;
        sW[i] = w[((size_t)d * 32 + cc) * 9 + t];
    }

    const float* in = (MODE == 0) ? g_acc : g_h2;
    for (int i = tid; i < 32 * 324; i += 256) {
        int cc = i / 324; int rem = i % 324;
        int yy = rem / 18, xx = rem % 18;
        int gy = ty0 + yy - 1, gx = tx0 + xx - 1;
        float v = 0.f;
        if ((unsigned)gy < 192u && (unsigned)gx < 192u) {
            v = in[(((size_t)n * DIMC + cc) * 192 + gy) * 192 + gx];
            if (MODE == 1) v = fmaxf(fmaf(v, g_scale2[cc], g_shift2[cc]), 0.f);
        }
        sIn[i] = v;
    }
    __syncthreads();

    int pg = tid & 63, d0 = (tid >> 6) * 8;
    int px = pg & 15, pyb = pg >> 4;

    ull acc2[4][4];
#pragma unroll
    for (int j = 0; j < 4; j++)
#pragma unroll
        for (int k = 0; k < 4; k++) acc2[j][k] = 0ull;

    for (int cc = 0; cc < 32; cc++) {
        const float* ib = &sIn[cc * 324];
        const float* wb = &sW[cc * 288 + d0];
#pragma unroll
        for (int t = 0; t < 9; t++) {
            int ky = t / 3, kx = t % 3;
            const ull* wp = (const ull*)(wb + t * 32);
            ull w0 = wp[0], w1r = wp[1], w2 = wp[2], w3 = wp[3];
#pragma unroll
            for (int j = 0; j < 4; j++) {
                float xv = ib[(pyb + 4 * j + ky) * 18 + px + kx];
                ull xp = pack2(xv);
                fma2(acc2[j][0], xp, w0);
                fma2(acc2[j][1], xp, w1r);
                fma2(acc2[j][2], xp, w2);
                fma2(acc2[j][3], xp, w3);
            }
        }
    }

    float bia[8];
#pragma unroll
    for (int k = 0; k < 8; k++) bia[k] = b[d0 + k];

    float* outp = (MODE == 0) ? g_h2 : out_ext;
    float sl[8], ql[8];
#pragma unroll
    for (int k = 0; k < 8; k++) { sl[k] = 0.f; ql[k] = 0.f; }

#pragma unroll
    for (int j = 0; j < 4; j++) {
        int oy = ty0 + pyb + 4 * j, ox = tx0 + px;
        float vv[8];
#pragma unroll
        for (int k2 = 0; k2 < 4; k2++) {
            float lo, hi;
            unpack2(acc2[j][k2], lo, hi);
            vv[2 * k2]     = lo + bia[2 * k2];
            vv[2 * k2 + 1] = hi + bia[2 * k2 + 1];
        }
#pragma unroll
        for (int k = 0; k < 8; k++) {
            float v = vv[k];
            outp[(((size_t)n * DIMC + d0 + k) * 192 + oy) * 192 + ox] = v;
            sl[k] += v; ql[k] += v * v;
        }
    }
#pragma unroll
    for (int k = 0; k < 8; k++) {
        atomicAdd(&sS[d0 + k], sl[k]);
        atomicAdd(&sQ[d0 + k], ql[k]);
    }
    __syncthreads();
    int bid = (blockIdx.z * gridDim.y + blockIdx.y) * gridDim.x + blockIdx.x;
    float* part = (MODE == 0) ? g_part2 : g_part3;
    if (tid < DIMC) {
        part[((size_t)bid * DIMC + tid) * 2 + 0] = sS[tid];
        part[((size_t)bid * DIMC + tid) * 2 + 1] = sQ[tid];
    }
}

// ---------------- final in-place BN3 + ReLU ---------------------------------
__global__ void k_final(float* __restrict__ out) {
    size_t i = ((size_t)blockIdx.x * 256 + threadIdx.x) * 4;
    int c = (int)((i / APIX) & 31);
    float sc = g_scale3[c], sh = g_shift3[c];
    float4 v = *(float4*)(out + i);
    v.x = fmaxf(fmaf(v.x, sc, sh), 0.f);
    v.y = fmaxf(fmaf(v.y, sc, sh), 0.f);
    v.z = fmaxf(fmaf(v.z, sc, sh), 0.f);
    v.w = fmaxf(fmaf(v.w, sc, sh), 0.f);
    *(float4*)(out + i) = v;
}

// ---------------- launch -----------------------------------------------------
extern "C" void kernel_launch(void* const* d_in, const int* in_sizes, int n_in,
                              void* d_out, int out_size) {
    const float* x   = (const float*)d_in[0];
    const float* w1  = (const float*)d_in[1];
    const float* b1  = (const float*)d_in[2];
    const float* g1  = (const float*)d_in[3];
    const float* be1 = (const float*)d_in[4];
    const float* w2  = (const float*)d_in[5];
    const float* b2  = (const float*)d_in[6];
    const float* g2  = (const float*)d_in[7];
    const float* be2 = (const float*)d_in[8];
    const float* w3  = (const float*)d_in[9];
    const float* b3  = (const float*)d_in[10];
    const float* g3  = (const float*)d_in[11];
    const float* be3 = (const float*)d_in[12];
    float* out = (float*)d_out;

    const int dhtSmem  = 4 * 192 * 20 * 4 + 2 * 520 * 16 + 2 * 528 * 4 + 8 * 4; // 82336
    const int convSmem = (32 * 324 + 32 * 9 * 32) * 4;                          // 78336
    cudaFuncSetAttribute(k_dhtg,       cudaFuncAttributeMaxDynamicSharedMemorySize, dhtSmem);
    cudaFuncSetAttribute(k_conv3x3<0>, cudaFuncAttributeMaxDynamicSharedMemorySize, convSmem);
    cudaFuncSetAttribute(k_conv3x3<1>, cudaFuncAttributeMaxDynamicSharedMemorySize, convSmem);

    // k_dhtg stays at launch index 3 (profiled slot)
    k_runs<<<dim3(NA, HH), 128>>>();
    k_conv1<<<512, 256>>>(x, w1, b1);
    k_prefboth<<<512, 256>>>(g1, be1);
    k_dhtg<<<dim3(48, 2, NB), 512, dhtSmem>>>();

    dim3 cgrid(12, 12, NB);
    k_conv3x3<0><<<cgrid, 256, convSmem>>>(w2, b2, nullptr);
    k_red<<<1, 256>>>(2, 2304, (float)(NB * APIX), g2, be2);

    k_conv3x3<1><<<cgrid, 256, convSmem>>>(w3, b3, out);
    k_red<<<1, 256>>>(3, 2304, (float)(NB * APIX), g3, be3);

    k_final<<<(NB * DIMC * APIX) / (256 * 4), 256>>>(out);
}

// round 7
// speedup vs baseline: 1.1325x; 1.1325x over previous
#include <cuda_runtime.h>
#include <math.h>

#define NB   16
#define CINC 256
#define DIMC 32
#define HH   128
#define WW   128
#define PIX  (HH*WW)          // 16384
#define NA   192
#define NR   192
#define APIX (NA*NR)          // 36864
#define BN_EPS 1e-5f
#define RUNCAP 132

typedef unsigned long long ull;

__device__ __forceinline__ void fma2(ull& d, ull a, ull b) {
    asm("fma.rn.f32x2 %0, %1, %2, %0;" : "+l"(d) : "l"(a), "l"(b));
}
__device__ __forceinline__ ull pack2(float x) {
    ull r; asm("mov.b64 %0, {%1, %1};" : "=l"(r) : "f"(x)); return r;
}
__device__ __forceinline__ void unpack2(ull v, float& lo, float& hi) {
    asm("mov.b64 {%0, %1}, %2;" : "=f"(lo), "=f"(hi) : "l"(v));
}

// ---------------- device scratch ----------------
__device__ unsigned int  g_runs[(size_t)NA * HH * RUNCAP];      // [a][line][slot] = t | r<<8
__device__ int           g_nrun[NA * HH];
__device__ float         g_h1[(size_t)NB * PIX * DIMC];         // [n][p][c]
__device__ float         g_pref[(size_t)NB * HH * 129 * DIMC];  // [n][y][x+1][c]
__device__ float         g_prefy[(size_t)NB * HH * 129 * DIMC]; // [n][x][y+1][c]
__device__ float         g_acc[(size_t)NB * DIMC * NA * NR];    // [n][c][a][r]
__device__ float         g_h2[(size_t)NB * DIMC * NA * NR];
__device__ float         g_part1[512  * DIMC * 2];
__device__ float         g_part2[2304 * DIMC * 2];
__device__ float         g_part3[2304 * DIMC * 2];
__device__ float         g_scale2[DIMC], g_shift2[DIMC];
__device__ float         g_scale3[DIMC], g_shift3[DIMC];

// ---------------- conv1 (1x1, FFMA2) + BN1 partial stats --------------------
__global__ __launch_bounds__(256) void k_conv1(const float* __restrict__ x,
                                               const float* __restrict__ w1,
                                               const float* __restrict__ b1) {
    __shared__ float sW[CINC * DIMC];
    __shared__ float sX[4][512];
    __shared__ float sS[DIMC], sQ[DIMC];

    int tid = threadIdx.x;
    int n  = blockIdx.x >> 5;
    int p0 = (blockIdx.x & 31) * 512;

    for (int i = tid; i < CINC * DIMC; i += 256) {
        int ci = i >> 5, d = i & 31;
        sW[i] = w1[d * CINC + ci];
    }
    if (tid < DIMC) { sS[tid] = 0.f; sQ[tid] = 0.f; }

    int pl = tid & 63;
    int d0 = (tid >> 6) * 8;

    ull acc2[8][4];
#pragma unroll
    for (int j = 0; j < 8; j++)
#pragma unroll
        for (int k = 0; k < 4; k++) acc2[j][k] = 0ull;

    const float* xb = x + (size_t)n * CINC * PIX + p0;

    for (int cc = 0; cc < CINC; cc += 4) {
        __syncthreads();
        for (int i = tid; i < 4 * 512; i += 256) {
            int cl = i >> 9, pp = i & 511;
            sX[cl][pp] = xb[(size_t)(cc + cl) * PIX + pp];
        }
        __syncthreads();
#pragma unroll
        for (int cl = 0; cl < 4; cl++) {
            float xv[8];
#pragma unroll
            for (int j = 0; j < 8; j++) xv[j] = sX[cl][pl + 64 * j];
            const ull* wp = (const ull*)&sW[(cc + cl) * DIMC + d0];
            ull w0 = wp[0], w1r = wp[1], w2 = wp[2], w3 = wp[3];
#pragma unroll
            for (int j = 0; j < 8; j++) {
                ull xp = pack2(xv[j]);
                fma2(acc2[j][0], xp, w0);
                fma2(acc2[j][1], xp, w1r);
                fma2(acc2[j][2], xp, w2);
                fma2(acc2[j][3], xp, w3);
            }
        }
    }

    float bia[8];
#pragma unroll
    for (int k = 0; k < 8; k++) bia[k] = b1[d0 + k];

    float* hb = g_h1 + ((size_t)n * PIX + p0) * DIMC;
    float sl[8], ql[8];
#pragma unroll
    for (int k = 0; k < 8; k++) { sl[k] = 0.f; ql[k] = 0.f; }

#pragma unroll
    for (int j = 0; j < 8; j++) {
        float vv[8];
#pragma unroll
        for (int k2 = 0; k2 < 4; k2++) {
            float lo, hi;
            unpack2(acc2[j][k2], lo, hi);
            vv[2 * k2]     = lo + bia[2 * k2];
            vv[2 * k2 + 1] = hi + bia[2 * k2 + 1];
        }
#pragma unroll
        for (int k = 0; k < 8; k++) { sl[k] += vv[k]; ql[k] += vv[k] * vv[k]; }
        float* op = hb + (size_t)(pl + 64 * j) * DIMC + d0;
        *(float4*)op       = make_float4(vv[0], vv[1], vv[2], vv[3]);
        *(float4*)(op + 4) = make_float4(vv[4], vv[5], vv[6], vv[7]);
    }
#pragma unroll
    for (int k = 0; k < 8; k++) {
        atomicAdd(&sS[d0 + k], sl[k]);
        atomicAdd(&sQ[d0 + k], ql[k]);
    }
    __syncthreads();
    if (tid < DIMC) {
        g_part1[(blockIdx.x * DIMC + tid) * 2 + 0] = sS[tid];
        g_part1[(blockIdx.x * DIMC + tid) * 2 + 1] = sQ[tid];
    }
}

// ---------------- combo: prefixes (blocks 0..511) + run lists (512..12799) ---
// Run blocks: one angle each (sin/cos computed ONCE by thread 0), two lines.
__global__ __launch_bounds__(256) void k_combo(const float* __restrict__ g1,
                                               const float* __restrict__ be1) {
    __shared__ float rs[8][32], rq[8][32], ssc[32], ssh[32];
    __shared__ double stc, sts;
    __shared__ int sr[256];
    __shared__ int swcnt[8], swoff[8];

    int bid = blockIdx.x;
    int tid = threadIdx.x;

    if (bid < 512) {
        // ---- BN1 reduce (redundant per block; g_part1 is L2-resident) ----
        int ch = tid & 31, s = tid >> 5;
        float su = 0.f, q = 0.f;
        for (int b = s; b < 512; b += 8) {
            su += g_part1[((size_t)b * DIMC + ch) * 2 + 0];
            q  += g_part1[((size_t)b * DIMC + ch) * 2 + 1];
        }
        rs[s][ch] = su; rq[s][ch] = q;
        __syncthreads();
        if (tid < 32) {
            float S = 0.f, Q = 0.f;
            for (int t = 0; t < 8; t++) { S += rs[t][ch]; Q += rq[t][ch]; }
            float cnt = (float)(NB * PIX);
            float m   = S / cnt;
            float var = Q / cnt - m * m;
            float scv = g1[ch] * rsqrtf(var + BN_EPS);
            ssc[ch] = scv;
            ssh[ch] = be1[ch] - m * scv;
        }
        __syncthreads();

        int w = s, c = ch;
        float sc = ssc[c], sh = ssh[c];
        if (bid < 256) {
            int row = bid * 8 + w;                    // n*128 + y
            int n = row >> 7, y = row & 127;
            const float* hb = g_h1 + ((size_t)n * PIX + (size_t)y * WW) * DIMC + c;
            float* pb = g_pref + (size_t)row * 129 * DIMC + c;
            float sum = 0.f;
            pb[0] = 0.f;
#pragma unroll 8
            for (int x = 0; x < 128; x++) {
                float v = fmaxf(fmaf(hb[(size_t)x * DIMC], sc, sh), 0.f);
                sum += v;
                pb[(size_t)(x + 1) * DIMC] = sum;
            }
        } else {
            int idx = (bid - 256) * 8 + w;            // n*128 + x
            int n = idx >> 7, x = idx & 127;
            const float* hb = g_h1 + ((size_t)n * PIX + x) * DIMC + c;
            float* pb = g_prefy + (size_t)idx * 129 * DIMC + c;
            float sum = 0.f;
            pb[0] = 0.f;
#pragma unroll 8
            for (int y = 0; y < 128; y++) {
                float v = fmaxf(fmaf(hb[(size_t)y * WW * DIMC], sc, sh), 0.f);
                sum += v;
                pb[(size_t)(y + 1) * DIMC] = sum;
            }
        }
    } else {
        // ---- run-list builder: a = block angle, two lines per block --------
        int rid = bid - 512;                  // 0..12287
        int a = rid >> 6;                     // 192 angles
        int l0 = (rid & 63) * 2;
        int grp = tid >> 7;                   // 0/1
        int t = tid & 127;
        int line = l0 + grp;

        if (tid == 0) {
            double irho = 182.0 / 191.0;
            double th = (double)a * (3.141592653589793 / 192.0);
            stc = cos(th) / irho;
            sts = sin(th) / irho;
        }
        __syncthreads();

        bool xmode = (a >= 48 && a < 144);
        int xc = xmode ? t : line;
        int yc = xmode ? line : t;
        double v = __dadd_rn(__dmul_rn((double)(xc - 64), stc),
                             __dmul_rn((double)(yc - 64), sts));
        int r = (int)rint(v) + 96;
        r = min(max(r, 0), 191);
        sr[tid] = r;
        __syncthreads();

        int f = (t == 0) || (r != sr[tid - 1]);
        unsigned bal = __ballot_sync(0xffffffffu, f);
        int w = t >> 5, lane = t & 31;
        int pre = __popc(bal & ((1u << lane) - 1u));
        if (lane == 31) swcnt[grp * 4 + w] = __popc(bal);
        __syncthreads();
        if (t == 0) {
            int o = 0;
            for (int i = 0; i < 4; i++) { swoff[grp * 4 + i] = o; o += swcnt[grp * 4 + i]; }
            g_nrun[a * HH + line] = o;
            g_runs[((size_t)a * HH + line) * RUNCAP + o] = 128u;   // sentinel
        }
        __syncthreads();
        if (f) g_runs[((size_t)a * HH + line) * RUNCAP + swoff[grp * 4 + w] + pre] =
                   (unsigned)t | ((unsigned)r << 8);
    }
}

// ---------------- BN reduce (stages 2,3) -------------------------------------
__global__ void k_red(int which, int nb, float cnt,
                      const float* __restrict__ g, const float* __restrict__ be) {
    const float* part = (which == 2) ? g_part2 : g_part3;
    float* sc = (which == 2) ? g_scale2 : g_scale3;
    float* sh = (which == 2) ? g_shift2 : g_shift3;
    __shared__ float rs[8][32], rq[8][32];
    int ch = threadIdx.x & 31, s = threadIdx.x >> 5;
    float su = 0.f, q = 0.f;
    for (int b = s; b < nb; b += 8) {
        su += part[((size_t)b * DIMC + ch) * 2 + 0];
        q  += part[((size_t)b * DIMC + ch) * 2 + 1];
    }
    rs[s][ch] = su; rq[s][ch] = q;
    __syncthreads();
    if (threadIdx.x < 32) {
        float S = 0.f, Q = 0.f;
        for (int t = 0; t < 8; t++) { S += rs[t][ch]; Q += rq[t][ch]; }
        float m   = S / cnt;
        float var = Q / cnt - m * m;
        float scv = g[ch] * rsqrtf(var + BN_EPS);
        sc[ch] = scv;
        sh[ch] = be[ch] - m * scv;
    }
}

// ---------------- DHT gather: dual-axis runs, 16ch/block, carry chunks -------
__global__ __launch_bounds__(512) void k_dhtg() {
    extern __shared__ float sm[];
    float*    sAcc  = sm;                                    // [4][192][20]
    float4*   sRow  = (float4*)(sm + 4 * 192 * 20);          // [2][520]
    unsigned* sRuns = (unsigned*)(sRow + 2 * 520);           // [2][528]
    int*      sNr   = (int*)(sRuns + 2 * 528);               // [2][4]

    int tid = threadIdx.x;
    int n = blockIdx.z, ch0 = blockIdx.y * 16, a0 = blockIdx.x * 4;
    bool xmode = (a0 >= 48 && a0 < 144);

    for (int i = tid; i < 4 * 192 * 20; i += 512) sAcc[i] = 0.f;

    int w = tid >> 5, lane = tid & 31;
    int ga = w >> 2, ws = w & 3;
    int rsub = lane >> 2, c4 = lane & 3;
    int slot = ws * 8 + rsub;

    const float4* prefn = (const float4*)((xmode ? g_pref : g_prefy)
                                          + (size_t)n * HH * 129 * DIMC);
    int cbase = (int)blockIdx.y * 4;
    float* accA = sAcc + ga * 192 * 20;

    float4 ra, rc;
    unsigned ru0 = 0, ru1 = 0;
    int rn = 0;
    int aa0 = tid / RUNCAP, kk0 = tid - aa0 * RUNCAP;
    int idx1 = tid + 512;
    int aa1 = idx1 / RUNCAP, kk1 = idx1 - aa1 * RUNCAP;
    int m0 = (tid >> 2) * 8 + cbase + (tid & 3);
    int m1 = 128 * 8 + cbase + tid;

    {
        ra = prefn[m0];
        if (tid < 4) rc = prefn[m1];
        ru0 = g_runs[((size_t)(a0 + aa0) * HH + 0) * RUNCAP + kk0];
        if (tid < 16) ru1 = g_runs[((size_t)(a0 + aa1) * HH + 0) * RUNCAP + kk1];
        if (tid < 4)  rn  = g_nrun[(a0 + tid) * HH + 0];
    }

    for (int line = 0; line < 128; line++) {
        int bsel = line & 1;
        float4* buf = sRow + bsel * 520;
        unsigned* rbuf = sRuns + bsel * 528;
        buf[tid] = ra;
        if (tid < 4) buf[512 + tid] = rc;
        rbuf[tid] = ru0;
        if (tid < 16) rbuf[512 + tid] = ru1;
        if (tid < 4)  sNr[bsel * 4 + tid] = rn;
        __syncthreads();

        if (line < 127) {
            const float4* src = prefn + (size_t)(line + 1) * (129 * 8);
            ra = src[m0];
            if (tid < 4) rc = src[m1];
            ru0 = g_runs[((size_t)(a0 + aa0) * HH + line + 1) * RUNCAP + kk0];
            if (tid < 16) ru1 = g_runs[((size_t)(a0 + aa1) * HH + line + 1) * RUNCAP + kk1];
            if (tid < 4)  rn  = g_nrun[(a0 + tid) * HH + line + 1];
        }

        int nrun = sNr[bsel * 4 + ga];
        const unsigned* rl = rbuf + ga * RUNCAP;
        int chunk = (nrun + 31) >> 5;
        int lo = slot * chunk;
        int hi = min(lo + chunk, nrun);
        if (lo < nrun) {
            float4 ps = buf[(int)(rl[lo] & 255u) * 4 + c4];
            for (int i = lo; i < hi; i++) {
                unsigned rec = rl[i];
                int r  = (rec >> 8) & 255;
                int xe = (int)(rl[i + 1] & 255u);
                float4 pe = buf[xe * 4 + c4];
                float* ap = accA + r * 20 + c4 * 4;
                float4 av = *(float4*)ap;
                av.x += pe.x - ps.x; av.y += pe.y - ps.y;
                av.z += pe.z - ps.z; av.w += pe.w - ps.w;
                *(float4*)ap = av;
                ps = pe;
            }
        }
    }
    __syncthreads();

    for (int e = tid; e < 4 * 16 * NR; e += 512) {
        int r = e % NR;
        int t2 = e / NR;
        int c = t2 & 15, ga2 = t2 >> 4;
        g_acc[(((size_t)n * DIMC + ch0 + c) * NA + (a0 + ga2)) * NR + r] =
            sAcc[(ga2 * 192 + r) * 20 + c];
    }
}

// ---------------- 3x3 conv (FFMA2) — proven version -------------------------
template <int MODE>
__global__ __launch_bounds__(256) void k_conv3x3(const float* __restrict__ w,
                                                 const float* __restrict__ b,
                                                 float* __restrict__ out_ext) {
    extern __shared__ float sm[];
    float* sIn = sm;                 // 32*18*18
    float* sW  = sm + 32 * 324;      // 32*9*32
    __shared__ float sS[DIMC], sQ[DIMC];

    int tid = threadIdx.x;
    if (tid < DIMC) { sS[tid] = 0.f; sQ[tid] = 0.f; }

    int n   = blockIdx.z;
    int ty0 = blockIdx.y * 16, tx0 = blockIdx.x * 16;

    for (int i = tid; i < 32 * 9 * 32; i += 256) {
        int d = i & 31; int t = (i >> 5) % 9; int cc = i / 288;
        sW[i] = w[((size_t)d * 32 + cc) * 9 + t];
    }

    const float* in = (MODE == 0) ? g_acc : g_h2;
    for (int i = tid; i < 32 * 324; i += 256) {
        int cc = i / 324; int rem = i % 324;
        int yy = rem / 18, xx = rem % 18;
        int gy = ty0 + yy - 1, gx = tx0 + xx - 1;
        float v = 0.f;
        if ((unsigned)gy < 192u && (unsigned)gx < 192u) {
            v = in[(((size_t)n * DIMC + cc) * 192 + gy) * 192 + gx];
            if (MODE == 1) v = fmaxf(fmaf(v, g_scale2[cc], g_shift2[cc]), 0.f);
        }
        sIn[i] = v;
    }
    __syncthreads();

    int pg = tid & 63, d0 = (tid >> 6) * 8;
    int px = pg & 15, pyb = pg >> 4;

    ull acc2[4][4];
#pragma unroll
    for (int j = 0; j < 4; j++)
#pragma unroll
        for (int k = 0; k < 4; k++) acc2[j][k] = 0ull;

    for (int cc = 0; cc < 32; cc++) {
        const float* ib = &sIn[cc * 324];
        const float* wb = &sW[cc * 288 + d0];
#pragma unroll
        for (int t = 0; t < 9; t++) {
            int ky = t / 3, kx = t % 3;
            const ull* wp = (const ull*)(wb + t * 32);
            ull w0 = wp[0], w1r = wp[1], w2 = wp[2], w3 = wp[3];
#pragma unroll
            for (int j = 0; j < 4; j++) {
                float xv = ib[(pyb + 4 * j + ky) * 18 + px + kx];
                ull xp = pack2(xv);
                fma2(acc2[j][0], xp, w0);
                fma2(acc2[j][1], xp, w1r);
                fma2(acc2[j][2], xp, w2);
                fma2(acc2[j][3], xp, w3);
            }
        }
    }

    float bia[8];
#pragma unroll
    for (int k = 0; k < 8; k++) bia[k] = b[d0 + k];

    float* outp = (MODE == 0) ? g_h2 : out_ext;
    float sl[8], ql[8];
#pragma unroll
    for (int k = 0; k < 8; k++) { sl[k] = 0.f; ql[k] = 0.f; }

#pragma unroll
    for (int j = 0; j < 4; j++) {
        int oy = ty0 + pyb + 4 * j, ox = tx0 + px;
        float vv[8];
#pragma unroll
        for (int k2 = 0; k2 < 4; k2++) {
            float lo, hi;
            unpack2(acc2[j][k2], lo, hi);
            vv[2 * k2]     = lo + bia[2 * k2];
            vv[2 * k2 + 1] = hi + bia[2 * k2 + 1];
        }
#pragma unroll
        for (int k = 0; k < 8; k++) {
            float v = vv[k];
            outp[(((size_t)n * DIMC + d0 + k) * 192 + oy) * 192 + ox] = v;
            sl[k] += v; ql[k] += v * v;
        }
    }
#pragma unroll
    for (int k = 0; k < 8; k++) {
        atomicAdd(&sS[d0 + k], sl[k]);
        atomicAdd(&sQ[d0 + k], ql[k]);
    }
    __syncthreads();
    int bid = (blockIdx.z * gridDim.y + blockIdx.y) * gridDim.x + blockIdx.x;
    float* part = (MODE == 0) ? g_part2 : g_part3;
    if (tid < DIMC) {
        part[((size_t)bid * DIMC + tid) * 2 + 0] = sS[tid];
        part[((size_t)bid * DIMC + tid) * 2 + 1] = sQ[tid];
    }
}

// ---------------- final in-place BN3 + ReLU ---------------------------------
__global__ void k_final(float* __restrict__ out) {
    size_t i = ((size_t)blockIdx.x * 256 + threadIdx.x) * 4;
    int c = (int)((i / APIX) & 31);
    float sc = g_scale3[c], sh = g_shift3[c];
    float4 v = *(float4*)(out + i);
    v.x = fmaxf(fmaf(v.x, sc, sh), 0.f);
    v.y = fmaxf(fmaf(v.y, sc, sh), 0.f);
    v.z = fmaxf(fmaf(v.z, sc, sh), 0.f);
    v.w = fmaxf(fmaf(v.w, sc, sh), 0.f);
    *(float4*)(out + i) = v;
}

// ---------------- launch -----------------------------------------------------
extern "C" void kernel_launch(void* const* d_in, const int* in_sizes, int n_in,
                              void* d_out, int out_size) {
    const float* x   = (const float*)d_in[0];
    const float* w1  = (const float*)d_in[1];
    const float* b1  = (const float*)d_in[2];
    const float* g1  = (const float*)d_in[3];
    const float* be1 = (const float*)d_in[4];
    const float* w2  = (const float*)d_in[5];
    const float* b2  = (const float*)d_in[6];
    const float* g2  = (const float*)d_in[7];
    const float* be2 = (const float*)d_in[8];
    const float* w3  = (const float*)d_in[9];
    const float* b3  = (const float*)d_in[10];
    const float* g3  = (const float*)d_in[11];
    const float* be3 = (const float*)d_in[12];
    float* out = (float*)d_out;

    const int dhtSmem  = 4 * 192 * 20 * 4 + 2 * 520 * 16 + 2 * 528 * 4 + 8 * 4; // 82336
    const int convSmem = (32 * 324 + 32 * 9 * 32) * 4;                          // 78336
    cudaFuncSetAttribute(k_dhtg,       cudaFuncAttributeMaxDynamicSharedMemorySize, dhtSmem);
    cudaFuncSetAttribute(k_conv3x3<0>, cudaFuncAttributeMaxDynamicSharedMemorySize, convSmem);
    cudaFuncSetAttribute(k_conv3x3<1>, cudaFuncAttributeMaxDynamicSharedMemorySize, convSmem);

    // launch order: conv3x3<0> at index 3 (profiled slot)
    k_conv1<<<512, 256>>>(x, w1, b1);
    k_combo<<<512 + NA * 64, 256>>>(g1, be1);
    k_dhtg<<<dim3(48, 2, NB), 512, dhtSmem>>>();

    dim3 cgrid(12, 12, NB);
    k_conv3x3<0><<<cgrid, 256, convSmem>>>(w2, b2, nullptr);
    k_red<<<1, 256>>>(2, 2304, (float)(NB * APIX), g2, be2);

    k_conv3x3<1><<<cgrid, 256, convSmem>>>(w3, b3, out);
    k_red<<<1, 256>>>(3, 2304, (float)(NB * APIX), g3, be3);

    k_final<<<(NB * DIMC * APIX) / (256 * 4), 256>>>(out);
}

// round 8
// speedup vs baseline: 1.1868x; 1.0480x over previous
#include <cuda_runtime.h>
#include <math.h>

#define NB   16
#define CINC 256
#define DIMC 32
#define HH   128
#define WW   128
#define PIX  (HH*WW)          // 16384
#define NA   192
#define NR   192
#define APIX (NA*NR)          // 36864
#define BN_EPS 1e-5f
#define RUNCAP 132

typedef unsigned long long ull;

__device__ __forceinline__ void fma2(ull& d, ull a, ull b) {
    asm("fma.rn.f32x2 %0, %1, %2, %0;" : "+l"(d) : "l"(a), "l"(b));
}
__device__ __forceinline__ ull pack2(float x) {
    ull r; asm("mov.b64 %0, {%1, %1};" : "=l"(r) : "f"(x)); return r;
}
__device__ __forceinline__ void unpack2(ull v, float& lo, float& hi) {
    asm("mov.b64 {%0, %1}, %2;" : "=f"(lo), "=f"(hi) : "l"(v));
}

// ---------------- device scratch ----------------
__device__ unsigned int  g_runs[(size_t)NA * HH * RUNCAP];      // [a][line][slot] = t | r<<8
__device__ int           g_nrun[NA * HH];
__device__ float         g_h1[(size_t)NB * PIX * DIMC];         // [n][p][c]
__device__ float         g_pref[(size_t)NB * HH * 129 * DIMC];  // [n][y][x+1][c]
__device__ float         g_prefy[(size_t)NB * HH * 129 * DIMC]; // [n][x][y+1][c]
__device__ float         g_acc[(size_t)NB * DIMC * NA * NR];    // [n][c][a][r]
__device__ float         g_h2[(size_t)NB * DIMC * NA * NR];
__device__ float         g_part1[512  * DIMC * 2];
__device__ float         g_part2[2304 * DIMC * 2];
__device__ float         g_part3[2304 * DIMC * 2];
__device__ float         g_scale2[DIMC], g_shift2[DIMC];
__device__ float         g_scale3[DIMC], g_shift3[DIMC];

// ---------------- conv1 (1x1, FFMA2) + BN1 partial stats --------------------
__global__ __launch_bounds__(256, 2) void k_conv1(const float* __restrict__ x,
                                                  const float* __restrict__ w1,
                                                  const float* __restrict__ b1) {
    __shared__ float sW[CINC * DIMC];
    __shared__ float sX[4][512];
    __shared__ float sS[DIMC], sQ[DIMC];

    int tid = threadIdx.x;
    int n  = blockIdx.x >> 5;
    int p0 = (blockIdx.x & 31) * 512;

    for (int i = tid; i < CINC * DIMC; i += 256) {
        int ci = i >> 5, d = i & 31;
        sW[i] = w1[d * CINC + ci];
    }
    if (tid < DIMC) { sS[tid] = 0.f; sQ[tid] = 0.f; }

    int pl = tid & 63;
    int d0 = (tid >> 6) * 8;

    ull acc2[8][4];
#pragma unroll
    for (int j = 0; j < 8; j++)
#pragma unroll
        for (int k = 0; k < 4; k++) acc2[j][k] = 0ull;

    const float* xb = x + (size_t)n * CINC * PIX + p0;

    for (int cc = 0; cc < CINC; cc += 4) {
        __syncthreads();
        for (int i = tid; i < 4 * 512; i += 256) {
            int cl = i >> 9, pp = i & 511;
            sX[cl][pp] = xb[(size_t)(cc + cl) * PIX + pp];
        }
        __syncthreads();
#pragma unroll
        for (int cl = 0; cl < 4; cl++) {
            float xv[8];
#pragma unroll
            for (int j = 0; j < 8; j++) xv[j] = sX[cl][pl + 64 * j];
            const ull* wp = (const ull*)&sW[(cc + cl) * DIMC + d0];
            ull w0 = wp[0], w1r = wp[1], w2 = wp[2], w3 = wp[3];
#pragma unroll
            for (int j = 0; j < 8; j++) {
                ull xp = pack2(xv[j]);
                fma2(acc2[j][0], xp, w0);
                fma2(acc2[j][1], xp, w1r);
                fma2(acc2[j][2], xp, w2);
                fma2(acc2[j][3], xp, w3);
            }
        }
    }

    float bia[8];
#pragma unroll
    for (int k = 0; k < 8; k++) bia[k] = b1[d0 + k];

    float* hb = g_h1 + ((size_t)n * PIX + p0) * DIMC;
    float sl[8], ql[8];
#pragma unroll
    for (int k = 0; k < 8; k++) { sl[k] = 0.f; ql[k] = 0.f; }

#pragma unroll
    for (int j = 0; j < 8; j++) {
        float vv[8];
#pragma unroll
        for (int k2 = 0; k2 < 4; k2++) {
            float lo, hi;
            unpack2(acc2[j][k2], lo, hi);
            vv[2 * k2]     = lo + bia[2 * k2];
            vv[2 * k2 + 1] = hi + bia[2 * k2 + 1];
        }
#pragma unroll
        for (int k = 0; k < 8; k++) { sl[k] += vv[k]; ql[k] += vv[k] * vv[k]; }
        float* op = hb + (size_t)(pl + 64 * j) * DIMC + d0;
        *(float4*)op       = make_float4(vv[0], vv[1], vv[2], vv[3]);
        *(float4*)(op + 4) = make_float4(vv[4], vv[5], vv[6], vv[7]);
    }
#pragma unroll
    for (int k = 0; k < 8; k++) {
        atomicAdd(&sS[d0 + k], sl[k]);
        atomicAdd(&sQ[d0 + k], ql[k]);
    }
    __syncthreads();
    if (tid < DIMC) {
        g_part1[(blockIdx.x * DIMC + tid) * 2 + 0] = sS[tid];
        g_part1[(blockIdx.x * DIMC + tid) * 2 + 1] = sQ[tid];
    }
}

// ---------------- combo: prefixes (blocks 0..511) + run lists ---------------
__global__ __launch_bounds__(256) void k_combo(const float* __restrict__ g1,
                                               const float* __restrict__ be1) {
    __shared__ float rs[8][32], rq[8][32], ssc[32], ssh[32];
    __shared__ double stc, sts;
    __shared__ int sr[256];
    __shared__ int swcnt[8], swoff[8];

    int bid = blockIdx.x;
    int tid = threadIdx.x;

    if (bid < 512) {
        int ch = tid & 31, s = tid >> 5;
        float su = 0.f, q = 0.f;
        for (int b = s; b < 512; b += 8) {
            su += g_part1[((size_t)b * DIMC + ch) * 2 + 0];
            q  += g_part1[((size_t)b * DIMC + ch) * 2 + 1];
        }
        rs[s][ch] = su; rq[s][ch] = q;
        __syncthreads();
        if (tid < 32) {
            float S = 0.f, Q = 0.f;
            for (int t = 0; t < 8; t++) { S += rs[t][ch]; Q += rq[t][ch]; }
            float cnt = (float)(NB * PIX);
            float m   = S / cnt;
            float var = Q / cnt - m * m;
            float scv = g1[ch] * rsqrtf(var + BN_EPS);
            ssc[ch] = scv;
            ssh[ch] = be1[ch] - m * scv;
        }
        __syncthreads();

        int w = s, c = ch;
        float sc = ssc[c], sh = ssh[c];
        if (bid < 256) {
            int row = bid * 8 + w;
            int n = row >> 7, y = row & 127;
            const float* hb = g_h1 + ((size_t)n * PIX + (size_t)y * WW) * DIMC + c;
            float* pb = g_pref + (size_t)row * 129 * DIMC + c;
            float sum = 0.f;
            pb[0] = 0.f;
#pragma unroll 8
            for (int x = 0; x < 128; x++) {
                float v = fmaxf(fmaf(hb[(size_t)x * DIMC], sc, sh), 0.f);
                sum += v;
                pb[(size_t)(x + 1) * DIMC] = sum;
            }
        } else {
            int idx = (bid - 256) * 8 + w;
            int n = idx >> 7, x = idx & 127;
            const float* hb = g_h1 + ((size_t)n * PIX + x) * DIMC + c;
            float* pb = g_prefy + (size_t)idx * 129 * DIMC + c;
            float sum = 0.f;
            pb[0] = 0.f;
#pragma unroll 8
            for (int y = 0; y < 128; y++) {
                float v = fmaxf(fmaf(hb[(size_t)y * WW * DIMC], sc, sh), 0.f);
                sum += v;
                pb[(size_t)(y + 1) * DIMC] = sum;
            }
        }
    } else {
        int rid = bid - 512;
        int a = rid >> 6;
        int l0 = (rid & 63) * 2;
        int grp = tid >> 7;
        int t = tid & 127;
        int line = l0 + grp;

        if (tid == 0) {
            double irho = 182.0 / 191.0;
            double th = (double)a * (3.141592653589793 / 192.0);
            stc = cos(th) / irho;
            sts = sin(th) / irho;
        }
        __syncthreads();

        bool xmode = (a >= 48 && a < 144);
        int xc = xmode ? t : line;
        int yc = xmode ? line : t;
        double v = __dadd_rn(__dmul_rn((double)(xc - 64), stc),
                             __dmul_rn((double)(yc - 64), sts));
        int r = (int)rint(v) + 96;
        r = min(max(r, 0), 191);
        sr[tid] = r;
        __syncthreads();

        int f = (t == 0) || (r != sr[tid - 1]);
        unsigned bal = __ballot_sync(0xffffffffu, f);
        int w = t >> 5, lane = t & 31;
        int pre = __popc(bal & ((1u << lane) - 1u));
        if (lane == 31) swcnt[grp * 4 + w] = __popc(bal);
        __syncthreads();
        if (t == 0) {
            int o = 0;
            for (int i = 0; i < 4; i++) { swoff[grp * 4 + i] = o; o += swcnt[grp * 4 + i]; }
            g_nrun[a * HH + line] = o;
            g_runs[((size_t)a * HH + line) * RUNCAP + o] = 128u;
        }
        __syncthreads();
        if (f) g_runs[((size_t)a * HH + line) * RUNCAP + swoff[grp * 4 + w] + pre] =
                   (unsigned)t | ((unsigned)r << 8);
    }
}

// ---------------- BN reduce (stages 2,3) -------------------------------------
__global__ void k_red(int which, int nb, float cnt,
                      const float* __restrict__ g, const float* __restrict__ be) {
    const float* part = (which == 2) ? g_part2 : g_part3;
    float* sc = (which == 2) ? g_scale2 : g_scale3;
    float* sh = (which == 2) ? g_shift2 : g_shift3;
    __shared__ float rs[8][32], rq[8][32];
    int ch = threadIdx.x & 31, s = threadIdx.x >> 5;
    float su = 0.f, q = 0.f;
    for (int b = s; b < nb; b += 8) {
        su += part[((size_t)b * DIMC + ch) * 2 + 0];
        q  += part[((size_t)b * DIMC + ch) * 2 + 1];
    }
    rs[s][ch] = su; rq[s][ch] = q;
    __syncthreads();
    if (threadIdx.x < 32) {
        float S = 0.f, Q = 0.f;
        for (int t = 0; t < 8; t++) { S += rs[t][ch]; Q += rq[t][ch]; }
        float m   = S / cnt;
        float var = Q / cnt - m * m;
        float scv = g[ch] * rsqrtf(var + BN_EPS);
        sc[ch] = scv;
        sh[ch] = be[ch] - m * scv;
    }
}

// ---------------- DHT gather (unchanged) -------------------------------------
__global__ __launch_bounds__(512) void k_dhtg() {
    extern __shared__ float sm[];
    float*    sAcc  = sm;                                    // [4][192][20]
    float4*   sRow  = (float4*)(sm + 4 * 192 * 20);          // [2][520]
    unsigned* sRuns = (unsigned*)(sRow + 2 * 520);           // [2][528]
    int*      sNr   = (int*)(sRuns + 2 * 528);               // [2][4]

    int tid = threadIdx.x;
    int n = blockIdx.z, ch0 = blockIdx.y * 16, a0 = blockIdx.x * 4;
    bool xmode = (a0 >= 48 && a0 < 144);

    for (int i = tid; i < 4 * 192 * 20; i += 512) sAcc[i] = 0.f;

    int w = tid >> 5, lane = tid & 31;
    int ga = w >> 2, ws = w & 3;
    int rsub = lane >> 2, c4 = lane & 3;
    int slot = ws * 8 + rsub;

    const float4* prefn = (const float4*)((xmode ? g_pref : g_prefy)
                                          + (size_t)n * HH * 129 * DIMC);
    int cbase = (int)blockIdx.y * 4;
    float* accA = sAcc + ga * 192 * 20;

    float4 ra, rc;
    unsigned ru0 = 0, ru1 = 0;
    int rn = 0;
    int aa0 = tid / RUNCAP, kk0 = tid - aa0 * RUNCAP;
    int idx1 = tid + 512;
    int aa1 = idx1 / RUNCAP, kk1 = idx1 - aa1 * RUNCAP;
    int m0 = (tid >> 2) * 8 + cbase + (tid & 3);
    int m1 = 128 * 8 + cbase + tid;

    {
        ra = prefn[m0];
        if (tid < 4) rc = prefn[m1];
        ru0 = g_runs[((size_t)(a0 + aa0) * HH + 0) * RUNCAP + kk0];
        if (tid < 16) ru1 = g_runs[((size_t)(a0 + aa1) * HH + 0) * RUNCAP + kk1];
        if (tid < 4)  rn  = g_nrun[(a0 + tid) * HH + 0];
    }

    for (int line = 0; line < 128; line++) {
        int bsel = line & 1;
        float4* buf = sRow + bsel * 520;
        unsigned* rbuf = sRuns + bsel * 528;
        buf[tid] = ra;
        if (tid < 4) buf[512 + tid] = rc;
        rbuf[tid] = ru0;
        if (tid < 16) rbuf[512 + tid] = ru1;
        if (tid < 4)  sNr[bsel * 4 + tid] = rn;
        __syncthreads();

        if (line < 127) {
            const float4* src = prefn + (size_t)(line + 1) * (129 * 8);
            ra = src[m0];
            if (tid < 4) rc = src[m1];
            ru0 = g_runs[((size_t)(a0 + aa0) * HH + line + 1) * RUNCAP + kk0];
            if (tid < 16) ru1 = g_runs[((size_t)(a0 + aa1) * HH + line + 1) * RUNCAP + kk1];
            if (tid < 4)  rn  = g_nrun[(a0 + tid) * HH + line + 1];
        }

        int nrun = sNr[bsel * 4 + ga];
        const unsigned* rl = rbuf + ga * RUNCAP;
        int chunk = (nrun + 31) >> 5;
        int lo = slot * chunk;
        int hi = min(lo + chunk, nrun);
        if (lo < nrun) {
            float4 ps = buf[(int)(rl[lo] & 255u) * 4 + c4];
            for (int i = lo; i < hi; i++) {
                unsigned rec = rl[i];
                int r  = (rec >> 8) & 255;
                int xe = (int)(rl[i + 1] & 255u);
                float4 pe = buf[xe * 4 + c4];
                float* ap = accA + r * 20 + c4 * 4;
                float4 av = *(float4*)ap;
                av.x += pe.x - ps.x; av.y += pe.y - ps.y;
                av.z += pe.z - ps.z; av.w += pe.w - ps.w;
                *(float4*)ap = av;
                ps = pe;
            }
        }
    }
    __syncthreads();

    for (int e = tid; e < 4 * 16 * NR; e += 512) {
        int r = e % NR;
        int t2 = e / NR;
        int c = t2 & 15, ga2 = t2 >> 4;
        g_acc[(((size_t)n * DIMC + ch0 + c) * NA + (a0 + ga2)) * NR + r] =
            sAcc[(ga2 * 192 + r) * 20 + c];
    }
}

// ---------------- 3x3 conv: FFMA2 + register row-cache + cc prefetch --------
// sIn layout [cc][yy*20+xx]; thread = (px, 4 consecutive rows, 8 d)
template <int MODE>
__global__ __launch_bounds__(256, 2) void k_conv3x3(const float* __restrict__ w,
                                                    const float* __restrict__ b,
                                                    float* __restrict__ out_ext) {
    extern __shared__ float sm[];
    float* sIn = sm;                 // 32 * 360
    float* sW  = sm + 32 * 360;      // 32*9*32
    __shared__ float sS[DIMC], sQ[DIMC];

    int tid = threadIdx.x;
    if (tid < DIMC) { sS[tid] = 0.f; sQ[tid] = 0.f; }

    int n   = blockIdx.z;
    int ty0 = blockIdx.y * 16, tx0 = blockIdx.x * 16;

    for (int i = tid; i < 32 * 9 * 32; i += 256) {
        int d = i & 31; int t = (i >> 5) % 9; int cc = i / 288;
        sW[i] = w[((size_t)d * 32 + cc) * 9 + t];
    }

    // staging: thread owns (cc = tid>>3, xseg = tid&7)
    {
        int cc = tid >> 3, xseg = tid & 7;
        const float* in = (MODE == 0) ? g_acc : g_h2;
        const float* inb = in + ((size_t)n * DIMC + cc) * 192 * 192;
        float sc2 = 0.f, sh2 = 0.f;
        if (MODE == 1) { sc2 = g_scale2[cc]; sh2 = g_shift2[cc]; }
        float* sb = sIn + cc * 360;
#pragma unroll
        for (int yy = 0; yy < 18; yy++) {
            int gy = ty0 + yy - 1;
            bool yok = (unsigned)gy < 192u;
#pragma unroll
            for (int k = 0; k < 3; k++) {
                int xx = xseg + 8 * k;
                if (xx < 18) {
                    int gx = tx0 + xx - 1;
                    float v = 0.f;
                    if (yok && (unsigned)gx < 192u) {
                        v = inb[(size_t)gy * 192 + gx];
                        if (MODE == 1) v = fmaxf(fmaf(v, sc2, sh2), 0.f);
                    }
                    sb[yy * 20 + xx] = v;
                }
            }
        }
    }
    __syncthreads();

    int pg = tid & 63, d0 = (tid >> 6) * 8;
    int px = pg & 15, pyb = pg >> 4;            // rows pyb*4 .. pyb*4+3

    ull acc2[4][4];
#pragma unroll
    for (int j = 0; j < 4; j++)
#pragma unroll
        for (int k = 0; k < 4; k++) acc2[j][k] = 0ull;

    const float* ibase = &sIn[pyb * 80 + px];

    float xA[18], xB[18];
#pragma unroll
    for (int rr = 0; rr < 6; rr++)
#pragma unroll
        for (int dx = 0; dx < 3; dx++) xA[rr * 3 + dx] = ibase[rr * 20 + dx];

#pragma unroll 1
    for (int cc = 0; cc < 32; cc += 2) {
        // prefetch cc+1 into xB
        {
            const float* ib = ibase + (cc + 1) * 360;
#pragma unroll
            for (int rr = 0; rr < 6; rr++)
#pragma unroll
                for (int dx = 0; dx < 3; dx++) xB[rr * 3 + dx] = ib[rr * 20 + dx];
        }
        // compute cc with xA
        {
            const float* wb = &sW[cc * 288 + d0];
#pragma unroll
            for (int t = 0; t < 9; t++) {
                int ky = t / 3, kx = t % 3;
                const ull* wp = (const ull*)(wb + t * 32);
                ull w0 = wp[0], w1r = wp[1], w2 = wp[2], w3 = wp[3];
#pragma unroll
                for (int j = 0; j < 4; j++) {
                    ull xp = pack2(xA[(j + ky) * 3 + kx]);
                    fma2(acc2[j][0], xp, w0);
                    fma2(acc2[j][1], xp, w1r);
                    fma2(acc2[j][2], xp, w2);
                    fma2(acc2[j][3], xp, w3);
                }
            }
        }
        // prefetch cc+2 into xA
        if (cc + 2 < 32) {
            const float* ib = ibase + (cc + 2) * 360;
#pragma unroll
            for (int rr = 0; rr < 6; rr++)
#pragma unroll
                for (int dx = 0; dx < 3; dx++) xA[rr * 3 + dx] = ib[rr * 20 + dx];
        }
        // compute cc+1 with xB
        {
            const float* wb = &sW[(cc + 1) * 288 + d0];
#pragma unroll
            for (int t = 0; t < 9; t++) {
                int ky = t / 3, kx = t % 3;
                const ull* wp = (const ull*)(wb + t * 32);
                ull w0 = wp[0], w1r = wp[1], w2 = wp[2], w3 = wp[3];
#pragma unroll
                for (int j = 0; j < 4; j++) {
                    ull xp = pack2(xB[(j + ky) * 3 + kx]);
                    fma2(acc2[j][0], xp, w0);
                    fma2(acc2[j][1], xp, w1r);
                    fma2(acc2[j][2], xp, w2);
                    fma2(acc2[j][3], xp, w3);
                }
            }
        }
    }

    float bia[8];
#pragma unroll
    for (int k = 0; k < 8; k++) bia[k] = b[d0 + k];

    float* outp = (MODE == 0) ? g_h2 : out_ext;
    float sl[8], ql[8];
#pragma unroll
    for (int k = 0; k < 8; k++) { sl[k] = 0.f; ql[k] = 0.f; }

#pragma unroll
    for (int j = 0; j < 4; j++) {
        int oy = ty0 + pyb * 4 + j, ox = tx0 + px;
        float vv[8];
#pragma unroll
        for (int k2 = 0; k2 < 4; k2++) {
            float lo, hi;
            unpack2(acc2[j][k2], lo, hi);
            vv[2 * k2]     = lo + bia[2 * k2];
            vv[2 * k2 + 1] = hi + bia[2 * k2 + 1];
        }
#pragma unroll
        for (int k = 0; k < 8; k++) {
            float v = vv[k];
            outp[(((size_t)n * DIMC + d0 + k) * 192 + oy) * 192 + ox] = v;
            sl[k] += v; ql[k] += v * v;
        }
    }
#pragma unroll
    for (int k = 0; k < 8; k++) {
        atomicAdd(&sS[d0 + k], sl[k]);
        atomicAdd(&sQ[d0 + k], ql[k]);
    }
    __syncthreads();
    int bid = (blockIdx.z * gridDim.y + blockIdx.y) * gridDim.x + blockIdx.x;
    float* part = (MODE == 0) ? g_part2 : g_part3;
    if (tid < DIMC) {
        part[((size_t)bid * DIMC + tid) * 2 + 0] = sS[tid];
        part[((size_t)bid * DIMC + tid) * 2 + 1] = sQ[tid];
    }
}

// ---------------- final in-place BN3 + ReLU ---------------------------------
__global__ void k_final(float* __restrict__ out) {
    size_t i = ((size_t)blockIdx.x * 256 + threadIdx.x) * 4;
    int c = (int)((i / APIX) & 31);
    float sc = g_scale3[c], sh = g_shift3[c];
    float4 v = *(float4*)(out + i);
    v.x = fmaxf(fmaf(v.x, sc, sh), 0.f);
    v.y = fmaxf(fmaf(v.y, sc, sh), 0.f);
    v.z = fmaxf(fmaf(v.z, sc, sh), 0.f);
    v.w = fmaxf(fmaf(v.w, sc, sh), 0.f);
    *(float4*)(out + i) = v;
}

// ---------------- launch -----------------------------------------------------
extern "C" void kernel_launch(void* const* d_in, const int* in_sizes, int n_in,
                              void* d_out, int out_size) {
    const float* x   = (const float*)d_in[0];
    const float* w1  = (const float*)d_in[1];
    const float* b1  = (const float*)d_in[2];
    const float* g1  = (const float*)d_in[3];
    const float* be1 = (const float*)d_in[4];
    const float* w2  = (const float*)d_in[5];
    const float* b2  = (const float*)d_in[6];
    const float* g2  = (const float*)d_in[7];
    const float* be2 = (const float*)d_in[8];
    const float* w3  = (const float*)d_in[9];
    const float* b3  = (const float*)d_in[10];
    const float* g3  = (const float*)d_in[11];
    const float* be3 = (const float*)d_in[12];
    float* out = (float*)d_out;

    const int dhtSmem  = 4 * 192 * 20 * 4 + 2 * 520 * 16 + 2 * 528 * 4 + 8 * 4; // 82336
    const int convSmem = (32 * 360 + 32 * 9 * 32) * 4;                          // 82944
    cudaFuncSetAttribute(k_dhtg,       cudaFuncAttributeMaxDynamicSharedMemorySize, dhtSmem);
    cudaFuncSetAttribute(k_conv3x3<0>, cudaFuncAttributeMaxDynamicSharedMemorySize, convSmem);
    cudaFuncSetAttribute(k_conv3x3<1>, cudaFuncAttributeMaxDynamicSharedMemorySize, convSmem);

    // conv3x3<0> stays at launch index 3 (profiled slot)
    k_conv1<<<512, 256>>>(x, w1, b1);
    k_combo<<<512 + NA * 64, 256>>>(g1, be1);
    k_dhtg<<<dim3(48, 2, NB), 512, dhtSmem>>>();

    dim3 cgrid(12, 12, NB);
    k_conv3x3<0><<<cgrid, 256, convSmem>>>(w2, b2, nullptr);
    k_red<<<1, 256>>>(2, 2304, (float)(NB * APIX), g2, be2);

    k_conv3x3<1><<<cgrid, 256, convSmem>>>(w3, b3, out);
    k_red<<<1, 256>>>(3, 2304, (float)(NB * APIX), g3, be3);

    k_final<<<(NB * DIMC * APIX) / (256 * 4), 256>>>(out);
}